// round 1
// baseline (speedup 1.0000x reference)
#include <cuda_runtime.h>
#include <cstdint>

// ---------------- problem constants ----------------
constexpr int U = 100000;
constexpr int I = 50000;
constexpr int D = 64;        // embed dim
constexpr int E = 2000000;   // bipartite edges
constexpr int N = U + I;     // 150000
constexpr int E2 = 2 * E;    // symmetric (self loops handled analytically)
constexpr float EPS = 1e-12f;

// ---------------- device scratch (static, no allocs) ----------------
__device__ float g_deg [N];
__device__ float g_dinv[N];
__device__ int   g_cnt [N];
__device__ int   g_off [N];
__device__ int   g_cur [N];
__device__ int   g_bsum[256];
__device__ int2  g_edge[E2];               // {src, bitcast(nrm)}
__device__ float g_x  [(size_t)N * D];
__device__ float g_xn [(size_t)N * D];
__device__ float g_acc[(size_t)N * D];

// ---------------- init ----------------
__global__ void k_init() {
    int i = blockIdx.x * blockDim.x + threadIdx.x;
    if (i < N) { g_deg[i] = 1.0f; g_cnt[i] = 0; }   // self loop weight = 1
}

// degree (weighted) + edge count per destination
__global__ void k_deg(const float* __restrict__ ew,
                      const int* __restrict__ u_idx,
                      const int* __restrict__ i_idx) {
    int e = blockIdx.x * blockDim.x + threadIdx.x;
    if (e >= E) return;
    int u  = u_idx[e];
    int it = U + i_idx[e];
    float w = fmaxf(ew[e], 1e-6f);
    atomicAdd(&g_deg[u],  w);
    atomicAdd(&g_deg[it], w);
    atomicAdd(&g_cnt[u],  1);
    atomicAdd(&g_cnt[it], 1);
}

__global__ void k_dinv() {
    int i = blockIdx.x * blockDim.x + threadIdx.x;
    if (i < N) g_dinv[i] = rsqrtf(g_deg[i]);   // deg >= 1 always
}

// ---------------- exclusive scan over g_cnt (3-kernel) ----------------
__global__ void k_scan1() {
    __shared__ int sh[1024];
    int t = threadIdx.x;
    int i = blockIdx.x * 1024 + t;
    int v = (i < N) ? g_cnt[i] : 0;
    sh[t] = v;
    __syncthreads();
    #pragma unroll
    for (int off = 1; off < 1024; off <<= 1) {
        int add = (t >= off) ? sh[t - off] : 0;
        __syncthreads();
        sh[t] += add;
        __syncthreads();
    }
    if (i < N) g_off[i] = sh[t] - v;            // exclusive
    if (t == 1023) g_bsum[blockIdx.x] = sh[1023];
}

__global__ void k_scan2(int nblk) {
    if (threadIdx.x == 0 && blockIdx.x == 0) {
        int run = 0;
        for (int b = 0; b < nblk; b++) { int s = g_bsum[b]; g_bsum[b] = run; run += s; }
    }
}

__global__ void k_scan3() {
    int i = blockIdx.x * blockDim.x + threadIdx.x;
    if (i < N) {
        int o = g_off[i] + g_bsum[i >> 10];
        g_off[i] = o;
        g_cur[i] = o;
    }
}

// ---------------- CSR fill ----------------
__global__ void k_fill(const float* __restrict__ ew,
                       const int* __restrict__ u_idx,
                       const int* __restrict__ i_idx) {
    int e = blockIdx.x * blockDim.x + threadIdx.x;
    if (e >= E) return;
    int u  = u_idx[e];
    int it = U + i_idx[e];
    float w   = fmaxf(ew[e], 1e-6f);
    float nrm = g_dinv[u] * w * g_dinv[it];
    int nb = __float_as_int(nrm);
    int p  = atomicAdd(&g_cur[u], 1);
    g_edge[p] = make_int2(it, nb);
    int q  = atomicAdd(&g_cur[it], 1);
    g_edge[q] = make_int2(u, nb);
}

// ---------------- L0: user embeddings (l2norm) ----------------
__global__ void k_user(const float* __restrict__ user_w) {
    int gw = (blockIdx.x * blockDim.x + threadIdx.x) >> 5;
    int l  = threadIdx.x & 31;
    if (gw >= U) return;
    const float2* src = (const float2*)(user_w + (size_t)gw * D);
    float2 v = src[l];
    float ss = v.x * v.x + v.y * v.y;
    #pragma unroll
    for (int o = 16; o; o >>= 1) ss += __shfl_xor_sync(0xffffffffu, ss, o);
    float inv = 1.0f / fmaxf(sqrtf(ss), EPS);
    float2 r = make_float2(v.x * inv, v.y * inv);
    size_t base = (size_t)gw * D;
    ((float2*)(g_x   + base))[l] = r;
    ((float2*)(g_acc + base))[l] = r;
}

// ---------------- L0: item embeddings (gather + proj GEMV + l2norm) ----------------
__global__ void k_item(const float* __restrict__ audio,
                       const float* __restrict__ artw,
                       const float* __restrict__ albw,
                       const float* __restrict__ W,     // [64][128] row-major
                       const float* __restrict__ bvec,  // [64]
                       const int*   __restrict__ aid,
                       const int*   __restrict__ bid) {
    __shared__ float Wt[128 * 64];     // Wt[k][d] transposed -> conflict-free
    __shared__ float bs[64];
    __shared__ float feat[8][128];
    int t = threadIdx.x;
    for (int i = t; i < 128 * 64; i += blockDim.x) {
        int k = i >> 6, d = i & 63;
        Wt[i] = W[d * 128 + k];
    }
    if (t < 64) bs[t] = bvec[t];
    __syncthreads();

    int wid = t >> 5, l = t & 31;
    int gw = blockIdx.x * 8 + wid;
    int nw = gridDim.x * 8;
    for (int item = gw; item < I; item += nw) {
        int a  = aid[item];
        int b2 = bid[item];
        #pragma unroll
        for (int j = 0; j < 4; j++) {
            int k = l + j * 32;
            float f;
            if (k < 64) f = audio[(size_t)item * 64 + k];
            else        f = artw[(size_t)a * 64 + (k - 64)] + albw[(size_t)b2 * 64 + (k - 64)];
            feat[wid][k] = f;
        }
        __syncwarp();
        float y0 = bs[l], y1 = bs[l + 32];
        #pragma unroll 8
        for (int k = 0; k < 128; k++) {
            float f = feat[wid][k];
            y0 += f * Wt[k * 64 + l];
            y1 += f * Wt[k * 64 + l + 32];
        }
        float ss = y0 * y0 + y1 * y1;
        #pragma unroll
        for (int o = 16; o; o >>= 1) ss += __shfl_xor_sync(0xffffffffu, ss, o);
        float inv = 1.0f / fmaxf(sqrtf(ss), EPS);
        size_t base = (size_t)(U + item) * D;
        g_x  [base + l]      = y0 * inv;
        g_x  [base + l + 32] = y1 * inv;
        g_acc[base + l]      = y0 * inv;
        g_acc[base + l + 32] = y1 * inv;
        __syncwarp();
    }
}

// ---------------- SpMM layer: one warp per destination node ----------------
// dir==0: g_x -> g_xn ; dir==1: g_xn -> g_x.   Always acc += out.
__global__ void k_spmm(int dir) {
    int gw = (blockIdx.x * blockDim.x + threadIdx.x) >> 5;
    int l  = threadIdx.x & 31;
    if (gw >= N) return;
    const float* __restrict__ xin = dir ? g_xn : g_x;
    float* __restrict__ xout      = dir ? g_x  : g_xn;

    int   beg = g_off[gw];
    int   cnt = g_cnt[gw];
    float di  = g_dinv[gw];
    float sn  = di * di;                         // self-loop norm 1/deg

    float2 s = ((const float2*)(xin + (size_t)gw * D))[l];
    float ax = s.x * sn, ay = s.y * sn;

    int e = beg, end = beg + cnt;
    for (; e + 4 <= end; e += 4) {
        int2 e0 = g_edge[e], e1 = g_edge[e + 1], e2 = g_edge[e + 2], e3 = g_edge[e + 3];
        float2 v0 = ((const float2*)(xin + (size_t)e0.x * D))[l];
        float2 v1 = ((const float2*)(xin + (size_t)e1.x * D))[l];
        float2 v2 = ((const float2*)(xin + (size_t)e2.x * D))[l];
        float2 v3 = ((const float2*)(xin + (size_t)e3.x * D))[l];
        float n0 = __int_as_float(e0.y), n1 = __int_as_float(e1.y);
        float n2 = __int_as_float(e2.y), n3 = __int_as_float(e3.y);
        ax += n0 * v0.x; ay += n0 * v0.y;
        ax += n1 * v1.x; ay += n1 * v1.y;
        ax += n2 * v2.x; ay += n2 * v2.y;
        ax += n3 * v3.x; ay += n3 * v3.y;
    }
    for (; e < end; e++) {
        int2 ee = g_edge[e];
        float2 v = ((const float2*)(xin + (size_t)ee.x * D))[l];
        float nn = __int_as_float(ee.y);
        ax += nn * v.x; ay += nn * v.y;
    }

    size_t base = (size_t)gw * D;
    ((float2*)(xout + base))[l] = make_float2(ax, ay);
    float2* arow = (float2*)(g_acc + base);
    float2 a = arow[l];
    a.x += ax; a.y += ay;
    arow[l] = a;
}

// ---------------- final: out = l2norm(acc / 4) ----------------
__global__ void k_final(float* __restrict__ out) {
    int gw = (blockIdx.x * blockDim.x + threadIdx.x) >> 5;
    int l  = threadIdx.x & 31;
    if (gw >= N) return;
    size_t base = (size_t)gw * D;
    float2 a = ((const float2*)(g_acc + base))[l];
    a.x *= 0.25f; a.y *= 0.25f;
    float ss = a.x * a.x + a.y * a.y;
    #pragma unroll
    for (int o = 16; o; o >>= 1) ss += __shfl_xor_sync(0xffffffffu, ss, o);
    float inv = 1.0f / fmaxf(sqrtf(ss), EPS);
    ((float2*)(out + base))[l] = make_float2(a.x * inv, a.y * inv);
}

// ---------------- launcher ----------------
extern "C" void kernel_launch(void* const* d_in, const int* in_sizes, int n_in,
                              void* d_out, int out_size) {
    const float* user_w     = (const float*)d_in[0];
    const float* item_audio = (const float*)d_in[1];
    const float* artist_w   = (const float*)d_in[2];
    const float* album_w    = (const float*)d_in[3];
    const float* proj_W     = (const float*)d_in[4];
    const float* proj_b     = (const float*)d_in[5];
    const float* edge_w     = (const float*)d_in[6];
    const int*   u_idx      = (const int*)d_in[7];
    const int*   i_idx      = (const int*)d_in[8];
    const int*   artist_ids = (const int*)d_in[9];
    const int*   album_ids  = (const int*)d_in[10];
    float* out = (float*)d_out;

    const int TB = 256;
    int gN = (N + TB - 1) / TB;
    int gE = (E + TB - 1) / TB;
    int nblk = (N + 1023) / 1024;   // 147

    k_init <<<gN, TB>>>();
    k_deg  <<<gE, TB>>>(edge_w, u_idx, i_idx);
    k_dinv <<<gN, TB>>>();
    k_scan1<<<nblk, 1024>>>();
    k_scan2<<<1, 32>>>(nblk);
    k_scan3<<<gN, TB>>>();
    k_fill <<<gE, TB>>>(edge_w, u_idx, i_idx);

    int gU = (U * 32 + TB - 1) / TB;
    k_user <<<gU, TB>>>(user_w);
    k_item <<<1184, TB>>>(item_audio, artist_w, album_w, proj_W, proj_b,
                          artist_ids, album_ids);

    int gW = (N * 32 + TB - 1) / TB;
    k_spmm <<<gW, TB>>>(0);   // x  -> xn
    k_spmm <<<gW, TB>>>(1);   // xn -> x
    k_spmm <<<gW, TB>>>(0);   // x  -> xn
    k_final<<<gW, TB>>>(out);
}

// round 2
// speedup vs baseline: 1.0950x; 1.0950x over previous
#include <cuda_runtime.h>
#include <cuda_fp16.h>
#include <cstdint>

// ---------------- problem constants ----------------
constexpr int U = 100000;
constexpr int I = 50000;
constexpr int D = 64;        // embed dim
constexpr int E = 2000000;   // bipartite edges
constexpr int N = U + I;     // 150000
constexpr int E2 = 2 * E;    // symmetric (self loops handled analytically)
constexpr int NH = D / 2;    // half2 per row = 32
constexpr float EPS = 1e-12f;

// ---------------- device scratch (static, no allocs) ----------------
__device__ float   g_deg [N];
__device__ float   g_dinv[N];
__device__ int     g_cnt [N];
__device__ int     g_off [N];
__device__ int     g_cur [N];
__device__ int     g_bsum[256];
__device__ int2    g_edge[E2];                    // {src, bitcast(nrm)}
__device__ __half2 g_xl[4][(size_t)N * NH];       // layer outputs x0..x3 (fp16)

// ---------------- init ----------------
__global__ void k_init() {
    int i = blockIdx.x * blockDim.x + threadIdx.x;
    if (i < N) { g_deg[i] = 1.0f; g_cnt[i] = 0; }   // self loop weight = 1
}

// weighted degree + edge count per endpoint
__global__ void k_deg(const float* __restrict__ ew,
                      const int* __restrict__ u_idx,
                      const int* __restrict__ i_idx) {
    int e = blockIdx.x * blockDim.x + threadIdx.x;
    if (e >= E) return;
    int u  = u_idx[e];
    int it = U + i_idx[e];
    float w = fmaxf(ew[e], 1e-6f);
    atomicAdd(&g_deg[u],  w);
    atomicAdd(&g_deg[it], w);
    atomicAdd(&g_cnt[u],  1);
    atomicAdd(&g_cnt[it], 1);
}

__global__ void k_dinv() {
    int i = blockIdx.x * blockDim.x + threadIdx.x;
    if (i < N) g_dinv[i] = rsqrtf(g_deg[i]);   // deg >= 1 always
}

// ---------------- exclusive scan over g_cnt (3-kernel) ----------------
__global__ void k_scan1() {
    __shared__ int sh[1024];
    int t = threadIdx.x;
    int i = blockIdx.x * 1024 + t;
    int v = (i < N) ? g_cnt[i] : 0;
    sh[t] = v;
    __syncthreads();
    #pragma unroll
    for (int off = 1; off < 1024; off <<= 1) {
        int add = (t >= off) ? sh[t - off] : 0;
        __syncthreads();
        sh[t] += add;
        __syncthreads();
    }
    if (i < N) g_off[i] = sh[t] - v;            // exclusive
    if (t == 1023) g_bsum[blockIdx.x] = sh[1023];
}

__global__ void k_scan2(int nblk) {
    if (threadIdx.x == 0 && blockIdx.x == 0) {
        int run = 0;
        for (int b = 0; b < nblk; b++) { int s = g_bsum[b]; g_bsum[b] = run; run += s; }
    }
}

__global__ void k_scan3() {
    int i = blockIdx.x * blockDim.x + threadIdx.x;
    if (i < N) {
        int o = g_off[i] + g_bsum[i >> 10];
        g_off[i] = o;
        g_cur[i] = o;
    }
}

// ---------------- CSR fill ----------------
__global__ void k_fill(const float* __restrict__ ew,
                       const int* __restrict__ u_idx,
                       const int* __restrict__ i_idx) {
    int e = blockIdx.x * blockDim.x + threadIdx.x;
    if (e >= E) return;
    int u  = u_idx[e];
    int it = U + i_idx[e];
    float w   = fmaxf(ew[e], 1e-6f);
    float nrm = g_dinv[u] * w * g_dinv[it];
    int nb = __float_as_int(nrm);
    int p  = atomicAdd(&g_cur[u], 1);
    g_edge[p] = make_int2(it, nb);
    int q  = atomicAdd(&g_cur[it], 1);
    g_edge[q] = make_int2(u, nb);
}

// ---------------- L0: user embeddings (l2norm -> fp16) ----------------
__global__ void k_user(const float* __restrict__ user_w) {
    int gw = (blockIdx.x * blockDim.x + threadIdx.x) >> 5;
    int l  = threadIdx.x & 31;
    if (gw >= U) return;
    const float2* src = (const float2*)(user_w + (size_t)gw * D);
    float2 v = src[l];                 // cols 2l, 2l+1
    float ss = v.x * v.x + v.y * v.y;
    #pragma unroll
    for (int o = 16; o; o >>= 1) ss += __shfl_xor_sync(0xffffffffu, ss, o);
    float inv = 1.0f / fmaxf(sqrtf(ss), EPS);
    g_xl[0][(size_t)gw * NH + l] = __floats2half2_rn(v.x * inv, v.y * inv);
}

// ---------------- L0: item embeddings (gather + proj GEMV + l2norm -> fp16) ----------------
__global__ void k_item(const float* __restrict__ audio,
                       const float* __restrict__ artw,
                       const float* __restrict__ albw,
                       const float* __restrict__ W,     // [64][128] row-major
                       const float* __restrict__ bvec,  // [64]
                       const int*   __restrict__ aid,
                       const int*   __restrict__ bid) {
    __shared__ float2 Wt[128 * 32];    // Wt[k][l] = (W[2l][k], W[2l+1][k])
    __shared__ float  bs[64];
    __shared__ float  feat[8][128];
    int t = threadIdx.x;
    for (int i = t; i < 128 * 32; i += blockDim.x) {
        int k = i >> 5, l = i & 31;
        Wt[i] = make_float2(W[(2 * l) * 128 + k], W[(2 * l + 1) * 128 + k]);
    }
    if (t < 64) bs[t] = bvec[t];
    __syncthreads();

    int wid = t >> 5, l = t & 31;
    int gw = blockIdx.x * 8 + wid;
    int nw = gridDim.x * 8;
    for (int item = gw; item < I; item += nw) {
        int a  = aid[item];
        int b2 = bid[item];
        #pragma unroll
        for (int j = 0; j < 4; j++) {
            int k = l + j * 32;
            float f;
            if (k < 64) f = audio[(size_t)item * 64 + k];
            else        f = artw[(size_t)a * 64 + (k - 64)] + albw[(size_t)b2 * 64 + (k - 64)];
            feat[wid][k] = f;
        }
        __syncwarp();
        float y0 = bs[2 * l], y1 = bs[2 * l + 1];   // cols 2l, 2l+1
        #pragma unroll 8
        for (int k = 0; k < 128; k++) {
            float f = feat[wid][k];
            float2 w2 = Wt[k * 32 + l];
            y0 += f * w2.x;
            y1 += f * w2.y;
        }
        float ss = y0 * y0 + y1 * y1;
        #pragma unroll
        for (int o = 16; o; o >>= 1) ss += __shfl_xor_sync(0xffffffffu, ss, o);
        float inv = 1.0f / fmaxf(sqrtf(ss), EPS);
        g_xl[0][(size_t)(U + item) * NH + l] = __floats2half2_rn(y0 * inv, y1 * inv);
        __syncwarp();
    }
}

// ---------------- SpMM layer: one warp per destination node ----------------
__global__ void k_spmm(int lin, int lout) {
    int gw = (blockIdx.x * blockDim.x + threadIdx.x) >> 5;
    int l  = threadIdx.x & 31;
    if (gw >= N) return;
    const __half2* __restrict__ xin = g_xl[lin];
    __half2*       __restrict__ xout = g_xl[lout];

    int   beg = g_off[gw];
    int   cnt = g_cnt[gw];
    float di  = g_dinv[gw];
    float sn  = di * di;                               // self-loop norm 1/deg

    float2 s = __half22float2(xin[(size_t)gw * NH + l]);
    float ax = s.x * sn, ay = s.y * sn;

    int e = beg, end = beg + cnt;
    for (; e + 4 <= end; e += 4) {
        int2 e0 = g_edge[e], e1 = g_edge[e + 1], e2 = g_edge[e + 2], e3 = g_edge[e + 3];
        float2 v0 = __half22float2(xin[(size_t)e0.x * NH + l]);
        float2 v1 = __half22float2(xin[(size_t)e1.x * NH + l]);
        float2 v2 = __half22float2(xin[(size_t)e2.x * NH + l]);
        float2 v3 = __half22float2(xin[(size_t)e3.x * NH + l]);
        float n0 = __int_as_float(e0.y), n1 = __int_as_float(e1.y);
        float n2 = __int_as_float(e2.y), n3 = __int_as_float(e3.y);
        ax = fmaf(n0, v0.x, ax); ay = fmaf(n0, v0.y, ay);
        ax = fmaf(n1, v1.x, ax); ay = fmaf(n1, v1.y, ay);
        ax = fmaf(n2, v2.x, ax); ay = fmaf(n2, v2.y, ay);
        ax = fmaf(n3, v3.x, ax); ay = fmaf(n3, v3.y, ay);
    }
    for (; e < end; e++) {
        int2 ee = g_edge[e];
        float2 v = __half22float2(xin[(size_t)ee.x * NH + l]);
        float nn = __int_as_float(ee.y);
        ax = fmaf(nn, v.x, ax); ay = fmaf(nn, v.y, ay);
    }

    xout[(size_t)gw * NH + l] = __floats2half2_rn(ax, ay);
}

// ---------------- final: out = l2norm((x0+x1+x2+x3) / 4) ----------------
__global__ void k_final(float* __restrict__ out) {
    int gw = (blockIdx.x * blockDim.x + threadIdx.x) >> 5;
    int l  = threadIdx.x & 31;
    if (gw >= N) return;
    size_t idx = (size_t)gw * NH + l;
    float2 a0 = __half22float2(g_xl[0][idx]);
    float2 a1 = __half22float2(g_xl[1][idx]);
    float2 a2 = __half22float2(g_xl[2][idx]);
    float2 a3 = __half22float2(g_xl[3][idx]);
    float ax = (a0.x + a1.x + a2.x + a3.x) * 0.25f;
    float ay = (a0.y + a1.y + a2.y + a3.y) * 0.25f;
    float ss = ax * ax + ay * ay;
    #pragma unroll
    for (int o = 16; o; o >>= 1) ss += __shfl_xor_sync(0xffffffffu, ss, o);
    float inv = 1.0f / fmaxf(sqrtf(ss), EPS);
    ((float2*)(out + (size_t)gw * D))[l] = make_float2(ax * inv, ay * inv);
}

// ---------------- launcher ----------------
extern "C" void kernel_launch(void* const* d_in, const int* in_sizes, int n_in,
                              void* d_out, int out_size) {
    const float* user_w     = (const float*)d_in[0];
    const float* item_audio = (const float*)d_in[1];
    const float* artist_w   = (const float*)d_in[2];
    const float* album_w    = (const float*)d_in[3];
    const float* proj_W     = (const float*)d_in[4];
    const float* proj_b     = (const float*)d_in[5];
    const float* edge_w     = (const float*)d_in[6];
    const int*   u_idx      = (const int*)d_in[7];
    const int*   i_idx      = (const int*)d_in[8];
    const int*   artist_ids = (const int*)d_in[9];
    const int*   album_ids  = (const int*)d_in[10];
    float* out = (float*)d_out;

    const int TB = 256;
    int gN = (N + TB - 1) / TB;
    int gE = (E + TB - 1) / TB;
    int nblk = (N + 1023) / 1024;   // 147

    k_init <<<gN, TB>>>();
    k_deg  <<<gE, TB>>>(edge_w, u_idx, i_idx);
    k_dinv <<<gN, TB>>>();
    k_scan1<<<nblk, 1024>>>();
    k_scan2<<<1, 32>>>(nblk);
    k_scan3<<<gN, TB>>>();
    k_fill <<<gE, TB>>>(edge_w, u_idx, i_idx);

    int gU = (U * 32 + TB - 1) / TB;
    k_user <<<gU, TB>>>(user_w);
    k_item <<<1184, TB>>>(item_audio, artist_w, album_w, proj_W, proj_b,
                          artist_ids, album_ids);

    int gW = (N * 32 + TB - 1) / TB;
    k_spmm <<<gW, TB>>>(0, 1);
    k_spmm <<<gW, TB>>>(1, 2);
    k_spmm <<<gW, TB>>>(2, 3);
    k_final<<<gW, TB>>>(out);
}